// round 14
// baseline (speedup 1.0000x reference)
#include <cuda_runtime.h>
#include <cuda_fp16.h>
#include <cstdint>

// ---------------------------------------------------------------------------
// Problem constants
// ---------------------------------------------------------------------------
#define DIM_  1024
#define B_    8
#define TI_   2048
#define TJ_   2048
#define EPS_  1e-5f
#define NROWS_T (B_*TI_)   // 16384
#define NROWS_S (B_*TJ_)   // 16384
#define NXT_   (TJ_/256)   // 8 x-tiles per S row-block (qk uses TN=256)

// ---------------------------------------------------------------------------
// Scratch (device globals — sanctioned workaround for no-alloc rule)
// ---------------------------------------------------------------------------
__device__ __half g_ln_t[(size_t)NROWS_T * DIM_];
__device__ __half g_ln_k[(size_t)NROWS_S * DIM_];
__device__ __half g_ln_v[(size_t)NROWS_S * DIM_];
__device__ __half g_q  [(size_t)NROWS_T * DIM_];
__device__ __half g_k  [(size_t)NROWS_S * DIM_];
__device__ __half g_v  [(size_t)NROWS_S * DIM_];
__device__ __half g_P  [(size_t)B_ * TI_ * TJ_];  // exp(logits) (fp16, unnormalized)
__device__ float  g_Spart[(size_t)NXT_ * NROWS_T]; // per-x-tile row partial sums
__device__ float  g_rinv [(size_t)NROWS_T];        // 1 / row sum
__device__ __half g_Wq [(size_t)DIM_ * DIM_];     // RN-converted fp16 weights
__device__ __half g_Wk [(size_t)DIM_ * DIM_];
__device__ __half g_Wv [(size_t)DIM_ * DIM_];

// ---------------------------------------------------------------------------
// PTX helpers (legacy sm_80-class only — this toolchain's ptxas target is
// sm_103 non-'a', which rejects tcgen05/TMEM)
// ---------------------------------------------------------------------------
__device__ __forceinline__ uint32_t smem_u32(const void* p) {
    uint32_t a;
    asm("{ .reg .u64 t; cvta.to.shared.u64 t, %1; cvt.u32.u64 %0, t; }"
        : "=r"(a) : "l"(p));
    return a;
}

#define CP_ASYNC16(dst_u32, src_ptr) \
    asm volatile("cp.async.cg.shared.global [%0], [%1], 16;\n" \
                 :: "r"(dst_u32), "l"(src_ptr))
#define CP_COMMIT() asm volatile("cp.async.commit_group;\n" ::: "memory")
#define CP_WAIT(n)  asm volatile("cp.async.wait_group %0;\n" :: "n"(n) : "memory")

#define LDSM4(r0, r1, r2, r3, addr) \
    asm volatile("ldmatrix.sync.aligned.m8n8.x4.shared.b16 {%0,%1,%2,%3}, [%4];" \
                 : "=r"(r0), "=r"(r1), "=r"(r2), "=r"(r3) : "r"(addr))

#define LDSM4T(r0, r1, r2, r3, addr) \
    asm volatile("ldmatrix.sync.aligned.m8n8.x4.trans.shared.b16 {%0,%1,%2,%3}, [%4];" \
                 : "=r"(r0), "=r"(r1), "=r"(r2), "=r"(r3) : "r"(addr))

#define MMA_F16(d0, d1, d2, d3, a0, a1, a2, a3, b0, b1) \
    asm volatile( \
        "mma.sync.aligned.m16n8k16.row.col.f32.f16.f16.f32 " \
        "{%0,%1,%2,%3}, {%4,%5,%6,%7}, {%8,%9}, {%0,%1,%2,%3};" \
        : "+f"(d0), "+f"(d1), "+f"(d2), "+f"(d3) \
        : "r"(a0), "r"(a1), "r"(a2), "r"(a3), "r"(b0), "r"(b1))

// ---------------------------------------------------------------------------
// Shared GEMM body. 512 threads / 16 warps. CTA tile 128 x TN (TN=256 or 128).
// Warp tile 32 x (TN/4). BK=64, 4 stages, fp32 accumulate.
//   B_NN = false: C[m,n] = f(sum_k A[m,k]*B[n,k])   B: [N,K] row-major
//   B_NN = true : C[m,n] = f(sum_k A[m,k]*B[k,n])   B: [K,N] row-major
//   EXP_MODE:  C = exp(scale*dot) fp16 + deterministic per-CTA row sums
//   ROWSCALE:  C = dot * rinv[bm+m]  fp32
// ---------------------------------------------------------------------------
constexpr int TBM = 128, TBK = 64, STAGES = 4;
constexpr int NTHR = 512;
constexpr int A_BYTES = TBM * TBK * 2;               // 16 KB

template <int TN>
constexpr int smem_total() { return 1024 + STAGES * (A_BYTES + TN * TBK * 2); }

template <int TN, bool HAS_BIAS, bool OUT_HALF, bool EXP_MODE, bool ROWSCALE, bool B_NN>
__device__ __forceinline__
void gemm_body(const __half* __restrict__ A, const __half* __restrict__ Bm,
               const float* __restrict__ bias, void* __restrict__ Cv,
               int N, int K, float scale, int bm, int bn,
               float* __restrict__ rowpart, const float* __restrict__ rinv) {
    constexpr int NFRAG = TN / 32;                  // 8 or 4 n-fragments/warp
    constexpr int B_BYTES_T = TN * TBK * 2;
    constexpr int STAGE_BYTES = A_BYTES + B_BYTES_T;

    extern __shared__ char smem[];
    const uint32_t tiles = (smem_u32(smem) + 1023u) & ~1023u;

    const int tid  = threadIdx.x;
    const int lane = tid & 31;
    const int w    = tid >> 5;          // 0..15
    const int wm   = (w & 3) * 32;      // 4 warp rows of 32
    const int wn   = (w >> 2) * (TN / 4);  // 4 warp cols

    // per-lane ldmatrix base offsets (A: 128-byte rows)
    const int rrA = (lane & 7) + (((lane >> 3) & 1) << 3);
    const int csA = (lane >> 4) & 1;

    uint32_t Aoff[2];
    #pragma unroll
    for (int mf = 0; mf < 2; mf++) {
        const int row = wm + mf * 16 + rrA;
        Aoff[mf] = (uint32_t)(row * 128) + (uint32_t)((((row & 7) ^ csA) << 4));
    }

    // B-side fragment offsets
    uint32_t Boff[NFRAG / 2];
    if (B_NN) {
        // B tile: [64 k-rows][TN n-cols], TN*2 B/row, col16 ^= (row&7) swizzle.
        const int t  = lane >> 3;
        const int ii = lane & 7;
        const int rloc = ((t & 1) << 3) + ii;       // k row within k16
        const int cb   = (wn >> 3) + (t >> 1);      // base 16B col
        #pragma unroll
        for (int nfp = 0; nfp < NFRAG / 2; nfp++)
            Boff[nfp] = (uint32_t)(rloc * (TN * 2)) +
                        (uint32_t)((((cb + 2 * nfp) ^ ii) << 4));
    } else {
        const int rrB = (lane & 7) + (((lane >> 4) & 1) << 3);
        const int csB = (lane >> 3) & 1;
        #pragma unroll
        for (int nfp = 0; nfp < NFRAG / 2; nfp++) {
            const int row = wn + nfp * 16 + rrB;
            Boff[nfp] = (uint32_t)(row * 128) + (uint32_t)((((row & 7) ^ csB) << 4));
        }
    }

    float acc[2][NFRAG][4];
    #pragma unroll
    for (int mf = 0; mf < 2; mf++)
        #pragma unroll
        for (int nf = 0; nf < NFRAG; nf++)
            #pragma unroll
            for (int c = 0; c < 4; c++) acc[mf][nf][c] = 0.f;

    const int nst = K / TBK;

    // stage loader: swizzled 16B cp.async
    auto load_stage = [&](int i) {
        const int s = i & (STAGES - 1);
        const uint32_t ab = tiles + s * STAGE_BYTES;
        const uint32_t bb = ab + A_BYTES;
        const int k0 = i * TBK;
        #pragma unroll
        for (int j = 0; j < 2; j++) {
            const int c   = tid + NTHR * j;
            const int row = c >> 3;          // 0..127
            const int c8  = c & 7;           // 16B chunk (8 fp16)
            const uint32_t off = (uint32_t)(row * 128) +
                                 (uint32_t)(((c8 ^ (row & 7)) << 4));
            CP_ASYNC16(ab + off, A + (size_t)(bm + row) * K + k0 + c8 * 8);
        }
        if (B_NN) {
            #pragma unroll
            for (int j = 0; j < TN / 64; j++) {
                const int c   = tid + NTHR * j;      // 0..8*TN-1
                const int row = c / (TN / 8);        // k row 0..63
                const int c16 = c & (TN / 8 - 1);    // 16B col
                const uint32_t off = (uint32_t)(row * (TN * 2)) +
                                     (uint32_t)(((c16 ^ (row & 7)) << 4));
                CP_ASYNC16(bb + off, Bm + (size_t)(k0 + row) * N + bn + c16 * 8);
            }
        } else {
            #pragma unroll
            for (int j = 0; j < TN / 64; j++) {
                const int c   = tid + NTHR * j;
                const int row = c >> 3;          // 0..TN-1
                const int c8  = c & 7;
                const uint32_t off = (uint32_t)(row * 128) +
                                     (uint32_t)(((c8 ^ (row & 7)) << 4));
                CP_ASYNC16(bb + off, Bm + (size_t)(bn + row) * K + k0 + c8 * 8);
            }
        }
        CP_COMMIT();
    };

    load_stage(0); load_stage(1); load_stage(2);

    for (int i = 0; i < nst; i++) {
        if (i + STAGES - 2 >= nst) { CP_WAIT(0); } else { CP_WAIT(STAGES - 2); }
        __syncthreads();
        if (i + STAGES - 1 < nst) load_stage(i + STAGES - 1);

        const int s = i & (STAGES - 1);
        const uint32_t ab = tiles + s * STAGE_BYTES;
        const uint32_t bb = ab + A_BYTES;

        #pragma unroll
        for (int ks = 0; ks < 4; ks++) {     // 4 x k16 per BK=64 stage
            const uint32_t cx = (uint32_t)(ks << 5);
            uint32_t af[2][4];
            #pragma unroll
            for (int mf = 0; mf < 2; mf++)
                LDSM4(af[mf][0], af[mf][1], af[mf][2], af[mf][3],
                      (ab + Aoff[mf]) ^ cx);
            uint32_t bf[NFRAG][2];
            if (B_NN) {
                #pragma unroll
                for (int nfp = 0; nfp < NFRAG / 2; nfp++) {
                    uint32_t r0, r1, r2, r3;
                    LDSM4T(r0, r1, r2, r3,
                           bb + Boff[nfp] + (uint32_t)(ks * (TN * 32)));
                    bf[2 * nfp][0] = r0;  bf[2 * nfp][1] = r1;
                    bf[2 * nfp + 1][0] = r2;  bf[2 * nfp + 1][1] = r3;
                }
            } else {
                #pragma unroll
                for (int nfp = 0; nfp < NFRAG / 2; nfp++) {
                    uint32_t r0, r1, r2, r3;
                    LDSM4(r0, r1, r2, r3, (bb + Boff[nfp]) ^ cx);
                    bf[2 * nfp][0] = r0;  bf[2 * nfp][1] = r1;
                    bf[2 * nfp + 1][0] = r2;  bf[2 * nfp + 1][1] = r3;
                }
            }
            #pragma unroll
            for (int mf = 0; mf < 2; mf++)
                #pragma unroll
                for (int nf = 0; nf < NFRAG; nf++)
                    MMA_F16(acc[mf][nf][0], acc[mf][nf][1],
                            acc[mf][nf][2], acc[mf][nf][3],
                            af[mf][0], af[mf][1], af[mf][2], af[mf][3],
                            bf[nf][0], bf[nf][1]);
        }
    }

    // --- epilogue ---
    if (EXP_MODE) {
        // exp() of logits -> fp16 P', plus deterministic per-CTA row sums
        __shared__ float sh_part[4][TBM];
        __half* C = (__half*)Cv;
        const int wcol = w >> 2;     // 0..3 (warp column group)
        float rs0[2] = {0.f, 0.f};
        float rs1[2] = {0.f, 0.f};
        #pragma unroll
        for (int mf = 0; mf < 2; mf++) {
            const int r0 = bm + wm + mf * 16 + (lane >> 2);
            #pragma unroll
            for (int nf = 0; nf < NFRAG; nf++) {
                const int c0 = bn + wn + nf * 8 + 2 * (lane & 3);
                const float e00 = __expf(acc[mf][nf][0] * scale);
                const float e01 = __expf(acc[mf][nf][1] * scale);
                const float e10 = __expf(acc[mf][nf][2] * scale);
                const float e11 = __expf(acc[mf][nf][3] * scale);
                rs0[mf] += e00 + e01;
                rs1[mf] += e10 + e11;
                *reinterpret_cast<__half2*>(C + (size_t)r0 * N + c0) =
                    __floats2half2_rn(e00, e01);
                *reinterpret_cast<__half2*>(C + (size_t)(r0 + 8) * N + c0) =
                    __floats2half2_rn(e10, e11);
            }
        }
        // quad reduce (sum over lane&3 within each quad) — deterministic
        #pragma unroll
        for (int mf = 0; mf < 2; mf++) {
            #pragma unroll
            for (int o = 1; o <= 2; o <<= 1) {
                rs0[mf] += __shfl_xor_sync(0xffffffffu, rs0[mf], o);
                rs1[mf] += __shfl_xor_sync(0xffffffffu, rs1[mf], o);
            }
        }
        if ((lane & 3) == 0) {
            #pragma unroll
            for (int mf = 0; mf < 2; mf++) {
                const int r = wm + mf * 16 + (lane >> 2);
                sh_part[wcol][r]     = rs0[mf];
                sh_part[wcol][r + 8] = rs1[mf];
            }
        }
        __syncthreads();
        if (tid < TBM) {
            rowpart[bm + tid] = (sh_part[0][tid] + sh_part[1][tid]) +
                                (sh_part[2][tid] + sh_part[3][tid]);
        }
    } else {
        #pragma unroll
        for (int mf = 0; mf < 2; mf++) {
            const int r0 = bm + wm + mf * 16 + (lane >> 2);
            float ri0 = 1.f, ri1 = 1.f;
            if (ROWSCALE) { ri0 = rinv[r0]; ri1 = rinv[r0 + 8]; }
            #pragma unroll
            for (int nf = 0; nf < NFRAG; nf++) {
                const int c0 = bn + wn + nf * 8 + 2 * (lane & 3);
                float2 b2 = make_float2(0.f, 0.f);
                if (HAS_BIAS) b2 = *reinterpret_cast<const float2*>(bias + c0);
                float v00 = acc[mf][nf][0] * scale + b2.x;
                float v01 = acc[mf][nf][1] * scale + b2.y;
                float v10 = acc[mf][nf][2] * scale + b2.x;
                float v11 = acc[mf][nf][3] * scale + b2.y;
                if (ROWSCALE) { v00 *= ri0; v01 *= ri0; v10 *= ri1; v11 *= ri1; }
                if (OUT_HALF) {
                    __half* C = (__half*)Cv;
                    *reinterpret_cast<__half2*>(C + (size_t)r0 * N + c0) =
                        __floats2half2_rn(v00, v01);
                    *reinterpret_cast<__half2*>(C + (size_t)(r0 + 8) * N + c0) =
                        __floats2half2_rn(v10, v11);
                } else {
                    float* C = (float*)Cv;
                    *reinterpret_cast<float2*>(C + (size_t)r0 * N + c0) =
                        make_float2(v00, v01);
                    *reinterpret_cast<float2*>(C + (size_t)(r0 + 8) * N + c0) =
                        make_float2(v10, v11);
                }
            }
        }
    }
}

// Fused QKV projection: TN=128, one launch of 3072 CTAs (tail 0.25 wave).
__global__ __launch_bounds__(NTHR, 1)
void qkv_proj_kernel(const __half* __restrict__ ln_t, const __half* __restrict__ ln_k,
                     const __half* __restrict__ ln_v,
                     const __half* __restrict__ wq, const __half* __restrict__ wk,
                     const __half* __restrict__ wv,
                     const float* __restrict__ bq, const float* __restrict__ bk,
                     const float* __restrict__ bv,
                     __half* __restrict__ q, __half* __restrict__ k,
                     __half* __restrict__ v) {
    const int z = blockIdx.z;
    const __half* A  = (z == 0) ? ln_t : (z == 1) ? ln_k : ln_v;
    const __half* Bm = (z == 0) ? wq   : (z == 1) ? wk   : wv;
    const float* bias = (z == 0) ? bq  : (z == 1) ? bk   : bv;
    __half* C = (z == 0) ? q : (z == 1) ? k : v;
    gemm_body<128, true, true, false, false, false>(A, Bm, bias, C, DIM_, DIM_, 1.0f,
        blockIdx.y * TBM, blockIdx.x * 128, nullptr, nullptr);
}

// QK^T with exp epilogue: TN=256 (unchanged geometry).
__global__ __launch_bounds__(NTHR, 1)
void qk_exp_kernel(const __half* __restrict__ q, const __half* __restrict__ k,
                   __half* __restrict__ P, float* __restrict__ Spart) {
    const int z = blockIdx.z;
    const __half* A = q + (size_t)z * TI_ * DIM_;
    const __half* B = k + (size_t)z * TJ_ * DIM_;
    __half* C = P + (size_t)z * TI_ * TJ_;
    float* rowpart = Spart + (size_t)blockIdx.x * NROWS_T + (size_t)z * TI_;
    gemm_body<256, false, true, true, false, false>(A, B, nullptr, C, TJ_, DIM_,
        0.03125f, blockIdx.y * TBM, blockIdx.x * 256, rowpart, nullptr);
}

// PV with per-row normalization: TN=128 (1024 CTAs, tail 0.08 wave); V read NN.
__global__ __launch_bounds__(NTHR, 1)
void pv_kernel(const __half* __restrict__ P, const __half* __restrict__ v,
               float* __restrict__ out, const float* __restrict__ rinv) {
    const int z = blockIdx.z;
    const __half* A = P + (size_t)z * TI_ * TJ_;
    const __half* B = v + (size_t)z * TJ_ * DIM_;   // [K=TJ][N=DIM] row-major
    float* C = out + (size_t)z * TI_ * DIM_;
    gemm_body<128, false, false, false, true, true>(A, B, nullptr, C, DIM_, TJ_,
        1.0f, blockIdx.y * TBM, blockIdx.x * 128, nullptr, rinv + (size_t)z * TI_);
}

// ---------------------------------------------------------------------------
// Row-sum reduction: rinv[r] = 1 / sum_x Spart[x][r]   (deterministic order)
// ---------------------------------------------------------------------------
__global__ void rowinv_kernel(const float* __restrict__ Spart,
                              float* __restrict__ rinv) {
    const int r = blockIdx.x * blockDim.x + threadIdx.x;
    if (r < NROWS_T) {
        float s = 0.f;
        #pragma unroll
        for (int x = 0; x < NXT_; x++) s += Spart[(size_t)x * NROWS_T + r];
        rinv[r] = 1.0f / s;
    }
}

// ---------------------------------------------------------------------------
// Fused fp32 -> fp16 (RN) weight conversion: grid.z selects matrix
// ---------------------------------------------------------------------------
__global__ void cvt3_kernel(const float* __restrict__ w0, const float* __restrict__ w1,
                            const float* __restrict__ w2,
                            __half* __restrict__ o0, __half* __restrict__ o1,
                            __half* __restrict__ o2) {
    const int z = blockIdx.z;
    const float* in = (z == 0) ? w0 : (z == 1) ? w1 : w2;
    __half* out     = (z == 0) ? o0 : (z == 1) ? o1 : o2;
    const int i = blockIdx.x * blockDim.x + threadIdx.x;
    const float4 v = reinterpret_cast<const float4*>(in)[i];
    const __half2 h0 = __floats2half2_rn(v.x, v.y);
    const __half2 h1 = __floats2half2_rn(v.z, v.w);
    uint2 u;
    u.x = *reinterpret_cast<const uint32_t*>(&h0);
    u.y = *reinterpret_cast<const uint32_t*>(&h1);
    reinterpret_cast<uint2*>(out)[i] = u;
}

// ---------------------------------------------------------------------------
// Fused LayerNorm: one WARP per row of 1024 (8 rows/block); grid.z selects
// (input, gamma, beta, output) set. Output fp16 (RN).
// ---------------------------------------------------------------------------
__global__ __launch_bounds__(256)
void ln3_kernel(const float* __restrict__ x0, const float* __restrict__ x1,
                const float* __restrict__ x2,
                const float* __restrict__ g0, const float* __restrict__ b0,
                const float* __restrict__ g1, const float* __restrict__ b1,
                const float* __restrict__ g2, const float* __restrict__ b2,
                __half* __restrict__ o0, __half* __restrict__ o1,
                __half* __restrict__ o2) {
    const int z = blockIdx.z;
    const float* x     = (z == 0) ? x0 : (z == 1) ? x1 : x2;
    const float* gamma = (z == 0) ? g0 : (z == 1) ? g1 : g2;
    const float* beta  = (z == 0) ? b0 : (z == 1) ? b1 : b2;
    __half* out        = (z == 0) ? o0 : (z == 1) ? o1 : o2;

    const int warp = threadIdx.x >> 5, lane = threadIdx.x & 31;
    const size_t row = (size_t)blockIdx.x * 8 + warp;
    const float4* xr = reinterpret_cast<const float4*>(x + row * DIM_);

    float4 xv[8];
    float s = 0.f, s2 = 0.f;
    #pragma unroll
    for (int i = 0; i < 8; i++) {
        xv[i] = xr[lane + 32 * i];
        s  += xv[i].x + xv[i].y + xv[i].z + xv[i].w;
        s2 += xv[i].x*xv[i].x + xv[i].y*xv[i].y + xv[i].z*xv[i].z + xv[i].w*xv[i].w;
    }
    #pragma unroll
    for (int o = 16; o; o >>= 1) {
        s  += __shfl_xor_sync(0xffffffffu, s,  o);
        s2 += __shfl_xor_sync(0xffffffffu, s2, o);
    }
    const float mean = s * (1.0f / DIM_);
    const float var  = s2 * (1.0f / DIM_) - mean * mean;
    const float inv  = rsqrtf(var + EPS_);

    uint2* o2v = reinterpret_cast<uint2*>(out + row * DIM_);
    #pragma unroll
    for (int i = 0; i < 8; i++) {
        const float4 gv = reinterpret_cast<const float4*>(gamma)[lane + 32 * i];
        const float4 bv = reinterpret_cast<const float4*>(beta)[lane + 32 * i];
        const __half2 h0 = __floats2half2_rn((xv[i].x - mean) * inv * gv.x + bv.x,
                                             (xv[i].y - mean) * inv * gv.y + bv.y);
        const __half2 h1 = __floats2half2_rn((xv[i].z - mean) * inv * gv.z + bv.z,
                                             (xv[i].w - mean) * inv * gv.w + bv.w);
        uint2 u;
        u.x = *reinterpret_cast<const uint32_t*>(&h0);
        u.y = *reinterpret_cast<const uint32_t*>(&h1);
        o2v[lane + 32 * i] = u;
    }
}

// ---------------------------------------------------------------------------
// Launch
// ---------------------------------------------------------------------------
extern "C" void kernel_launch(void* const* d_in, const int* in_sizes, int n_in,
                              void* d_out, int out_size) {
    (void)in_sizes; (void)n_in; (void)out_size;
    const float* target   = (const float*)d_in[0];
    const float* source_k = (const float*)d_in[1];
    const float* source_v = (const float*)d_in[2];
    const float* Wq = (const float*)d_in[3];
    const float* bq = (const float*)d_in[4];
    const float* Wk = (const float*)d_in[5];
    const float* bk = (const float*)d_in[6];
    const float* Wv = (const float*)d_in[7];
    const float* bv = (const float*)d_in[8];
    const float* gt = (const float*)d_in[9];
    const float* bt = (const float*)d_in[10];
    const float* gk = (const float*)d_in[11];
    const float* bk_ln = (const float*)d_in[12];
    const float* gv = (const float*)d_in[13];
    const float* bv_ln = (const float*)d_in[14];
    float* out = (float*)d_out;

    __half *ln_t, *ln_k, *ln_v, *q, *k, *v, *P, *wq_h, *wk_h, *wv_h;
    float *Spart, *rinv;
    cudaGetSymbolAddress((void**)&ln_t, g_ln_t);
    cudaGetSymbolAddress((void**)&ln_k, g_ln_k);
    cudaGetSymbolAddress((void**)&ln_v, g_ln_v);
    cudaGetSymbolAddress((void**)&q,    g_q);
    cudaGetSymbolAddress((void**)&k,    g_k);
    cudaGetSymbolAddress((void**)&v,    g_v);
    cudaGetSymbolAddress((void**)&P,    g_P);
    cudaGetSymbolAddress((void**)&Spart, g_Spart);
    cudaGetSymbolAddress((void**)&rinv,  g_rinv);
    cudaGetSymbolAddress((void**)&wq_h, g_Wq);
    cudaGetSymbolAddress((void**)&wk_h, g_Wk);
    cudaGetSymbolAddress((void**)&wv_h, g_Wv);

    cudaFuncSetAttribute(qkv_proj_kernel,
        cudaFuncAttributeMaxDynamicSharedMemorySize, smem_total<128>());
    cudaFuncSetAttribute(qk_exp_kernel,
        cudaFuncAttributeMaxDynamicSharedMemorySize, smem_total<256>());
    cudaFuncSetAttribute(pv_kernel,
        cudaFuncAttributeMaxDynamicSharedMemorySize, smem_total<128>());

    // Weights -> fp16 (one launch)
    cvt3_kernel<<<dim3(DIM_ * DIM_ / 4 / 256, 1, 3), 256>>>(
        Wq, Wk, Wv, wq_h, wk_h, wv_h);

    // LayerNorms (one launch, warp-per-row, fp16 out)
    ln3_kernel<<<dim3(NROWS_T / 8, 1, 3), 256>>>(
        target, source_k, source_v,
        gt, bt, gk, bk_ln, gv, bv_ln,
        ln_t, ln_k, ln_v);

    // Fused Q/K/V projections: TN=128, 3072 CTAs
    qkv_proj_kernel<<<dim3(DIM_ / 128, NROWS_T / TBM, 3), NTHR, smem_total<128>()>>>(
        ln_t, ln_k, ln_v, wq_h, wk_h, wv_h, bq, bk, bv, q, k, v);

    // P' = exp((Q K^T) * DIM^-0.5)  (fp16) + per-x-tile row sums (TN=256)
    dim3 gS(TJ_ / 256, TI_ / TBM, B_);
    qk_exp_kernel<<<gS, NTHR, smem_total<256>()>>>(q, k, P, Spart);

    // rinv[r] = 1 / sum of partials
    rowinv_kernel<<<(NROWS_T + 255) / 256, 256>>>(Spart, rinv);

    // O = (P' V) * rinv, batched (fp32 out to d_out), V read NN, TN=128
    dim3 gO(DIM_ / 128, TI_ / TBM, B_);
    pv_kernel<<<gO, NTHR, smem_total<128>()>>>(P, v, out, rinv);
}

// round 17
// speedup vs baseline: 1.0504x; 1.0504x over previous
#include <cuda_runtime.h>
#include <cuda_fp16.h>
#include <cstdint>

// ---------------------------------------------------------------------------
// Problem constants
// ---------------------------------------------------------------------------
#define DIM_  1024
#define B_    8
#define TI_   2048
#define TJ_   2048
#define EPS_  1e-5f
#define NROWS_T (B_*TI_)   // 16384
#define NROWS_S (B_*TJ_)   // 16384
#define NXT_   (TJ_/256)   // 8 x-tiles per S row-block

// ---------------------------------------------------------------------------
// Scratch (device globals — sanctioned workaround for no-alloc rule)
// ---------------------------------------------------------------------------
__device__ __half g_ln_t[(size_t)NROWS_T * DIM_];
__device__ __half g_ln_k[(size_t)NROWS_S * DIM_];
__device__ __half g_ln_v[(size_t)NROWS_S * DIM_];
__device__ __half g_q  [(size_t)NROWS_T * DIM_];
__device__ __half g_k  [(size_t)NROWS_S * DIM_];
__device__ __half g_v  [(size_t)NROWS_S * DIM_];
__device__ __half g_P  [(size_t)B_ * TI_ * TJ_];  // exp(logits) (fp16, unnormalized)
__device__ float  g_Spart[(size_t)NXT_ * NROWS_T]; // per-x-tile row partial sums
__device__ float  g_rinv [(size_t)NROWS_T];        // 1 / row sum
__device__ __half g_Wq [(size_t)DIM_ * DIM_];     // RN-converted fp16 weights
__device__ __half g_Wk [(size_t)DIM_ * DIM_];
__device__ __half g_Wv [(size_t)DIM_ * DIM_];

// ---------------------------------------------------------------------------
// PTX helpers (legacy sm_80-class only — this toolchain's ptxas target is
// sm_103 non-'a', which rejects tcgen05/TMEM)
// ---------------------------------------------------------------------------
__device__ __forceinline__ uint32_t smem_u32(const void* p) {
    uint32_t a;
    asm("{ .reg .u64 t; cvta.to.shared.u64 t, %1; cvt.u32.u64 %0, t; }"
        : "=r"(a) : "l"(p));
    return a;
}

#define CP_ASYNC16(dst_u32, src_ptr) \
    asm volatile("cp.async.cg.shared.global [%0], [%1], 16;\n" \
                 :: "r"(dst_u32), "l"(src_ptr))
#define CP_COMMIT() asm volatile("cp.async.commit_group;\n" ::: "memory")
#define CP_WAIT(n)  asm volatile("cp.async.wait_group %0;\n" :: "n"(n) : "memory")

#define LDSM4(r0, r1, r2, r3, addr) \
    asm volatile("ldmatrix.sync.aligned.m8n8.x4.shared.b16 {%0,%1,%2,%3}, [%4];" \
                 : "=r"(r0), "=r"(r1), "=r"(r2), "=r"(r3) : "r"(addr))

#define LDSM4T(r0, r1, r2, r3, addr) \
    asm volatile("ldmatrix.sync.aligned.m8n8.x4.trans.shared.b16 {%0,%1,%2,%3}, [%4];" \
                 : "=r"(r0), "=r"(r1), "=r"(r2), "=r"(r3) : "r"(addr))

#define MMA_F16(d0, d1, d2, d3, a0, a1, a2, a3, b0, b1) \
    asm volatile( \
        "mma.sync.aligned.m16n8k16.row.col.f32.f16.f16.f32 " \
        "{%0,%1,%2,%3}, {%4,%5,%6,%7}, {%8,%9}, {%0,%1,%2,%3};" \
        : "+f"(d0), "+f"(d1), "+f"(d2), "+f"(d3) \
        : "r"(a0), "r"(a1), "r"(a2), "r"(a3), "r"(b0), "r"(b1))

// ---------------------------------------------------------------------------
// Shared GEMM body (device function). 512 threads / 16 warps, warp tile 32x64.
//   B_NN = false: C[m,n] = f(sum_k A[m,k]*B[n,k])   B: [N,K] row-major
//   B_NN = true : C[m,n] = f(sum_k A[m,k]*B[k,n])   B: [K,N] row-major
//                 (B loaded via ldmatrix.trans; leading dim of B = N)
//   EXP_MODE:  C = exp(scale*dot) fp16 + deterministic per-CTA row sums
//   ROWSCALE:  C = dot * rinv[bm+m]  fp32
//   CTA tile 128x256, BK=64, 4 stages, fp32 accumulate.  (R10-proven config)
// ---------------------------------------------------------------------------
constexpr int TBM = 128, TBN = 256, TBK = 64, STAGES = 4;
constexpr int NTHR = 512;
constexpr int A_BYTES = TBM * TBK * 2;               // 16 KB
constexpr int B_BYTES = TBN * TBK * 2;               // 32 KB
constexpr int STAGE_BYTES = A_BYTES + B_BYTES;       // 48 KB
constexpr int SMEM_TOTAL_GEMM = 1024 + STAGES * STAGE_BYTES;  // ~193 KB

template <bool HAS_BIAS, bool OUT_HALF, bool EXP_MODE, bool ROWSCALE, bool B_NN>
__device__ __forceinline__
void gemm_body(const __half* __restrict__ A, const __half* __restrict__ Bm,
               const float* __restrict__ bias, void* __restrict__ Cv,
               int N, int K, float scale, int bm, int bn,
               float* __restrict__ rowpart, const float* __restrict__ rinv) {
    extern __shared__ char smem[];
    const uint32_t tiles = (smem_u32(smem) + 1023u) & ~1023u;

    const int tid  = threadIdx.x;
    const int lane = tid & 31;
    const int w    = tid >> 5;          // 0..15
    const int wm   = (w & 3) * 32;      // 4 warp rows of 32
    const int wn   = (w >> 2) * 64;     // 4 warp cols of 64

    // per-lane ldmatrix base offsets (A: 128-byte rows)
    const int rrA = (lane & 7) + (((lane >> 3) & 1) << 3);
    const int csA = (lane >> 4) & 1;

    uint32_t Aoff[2];
    #pragma unroll
    for (int mf = 0; mf < 2; mf++) {
        const int row = wm + mf * 16 + rrA;
        Aoff[mf] = (uint32_t)(row * 128) + (uint32_t)((((row & 7) ^ csA) << 4));
    }

    // B-side fragment offsets
    uint32_t Boff[4];
    if (B_NN) {
        // B tile: [64 k-rows][256 n-cols], 512 B/row, col16 ^= (row&7) swizzle.
        const int t  = lane >> 3;
        const int ii = lane & 7;
        const int rloc = ((t & 1) << 3) + ii;       // k row within k16
        const int cb   = (wn >> 3) + (t >> 1);      // base 16B col
        #pragma unroll
        for (int nfp = 0; nfp < 4; nfp++)
            Boff[nfp] = (uint32_t)(rloc * 512) +
                        (uint32_t)((((cb + 2 * nfp) ^ ii) << 4));
    } else {
        const int rrB = (lane & 7) + (((lane >> 4) & 1) << 3);
        const int csB = (lane >> 3) & 1;
        #pragma unroll
        for (int nfp = 0; nfp < 4; nfp++) {
            const int row = wn + nfp * 16 + rrB;
            Boff[nfp] = (uint32_t)(row * 128) + (uint32_t)((((row & 7) ^ csB) << 4));
        }
    }

    float acc[2][8][4];
    #pragma unroll
    for (int mf = 0; mf < 2; mf++)
        #pragma unroll
        for (int nf = 0; nf < 8; nf++)
            #pragma unroll
            for (int c = 0; c < 4; c++) acc[mf][nf][c] = 0.f;

    const int nst = K / TBK;

    // stage loader: swizzled 16B cp.async (A: 2/thread, B: 4/thread @512thr)
    auto load_stage = [&](int i) {
        const int s = i & (STAGES - 1);
        const uint32_t ab = tiles + s * STAGE_BYTES;
        const uint32_t bb = ab + A_BYTES;
        const int k0 = i * TBK;
        #pragma unroll
        for (int j = 0; j < 2; j++) {
            const int c   = tid + NTHR * j;
            const int row = c >> 3;          // 0..127
            const int c8  = c & 7;           // 16B chunk (8 fp16)
            const uint32_t off = (uint32_t)(row * 128) +
                                 (uint32_t)(((c8 ^ (row & 7)) << 4));
            CP_ASYNC16(ab + off, A + (size_t)(bm + row) * K + k0 + c8 * 8);
        }
        if (B_NN) {
            #pragma unroll
            for (int j = 0; j < 4; j++) {
                const int c   = tid + NTHR * j;  // 0..2047
                const int row = c >> 5;          // k row 0..63
                const int c32 = c & 31;          // 16B col 0..31
                const uint32_t off = (uint32_t)(row * 512) +
                                     (uint32_t)(((c32 ^ (row & 7)) << 4));
                CP_ASYNC16(bb + off, Bm + (size_t)(k0 + row) * N + bn + c32 * 8);
            }
        } else {
            #pragma unroll
            for (int j = 0; j < 4; j++) {
                const int c   = tid + NTHR * j;
                const int row = c >> 3;          // 0..255
                const int c8  = c & 7;
                const uint32_t off = (uint32_t)(row * 128) +
                                     (uint32_t)(((c8 ^ (row & 7)) << 4));
                CP_ASYNC16(bb + off, Bm + (size_t)(bn + row) * K + k0 + c8 * 8);
            }
        }
        CP_COMMIT();
    };

    load_stage(0); load_stage(1); load_stage(2);

    for (int i = 0; i < nst; i++) {
        if (i + STAGES - 2 >= nst) { CP_WAIT(0); } else { CP_WAIT(STAGES - 2); }
        __syncthreads();
        if (i + STAGES - 1 < nst) load_stage(i + STAGES - 1);

        const int s = i & (STAGES - 1);
        const uint32_t ab = tiles + s * STAGE_BYTES;
        const uint32_t bb = ab + A_BYTES;

        #pragma unroll
        for (int ks = 0; ks < 4; ks++) {     // 4 x k16 per BK=64 stage
            const uint32_t cx = (uint32_t)(ks << 5);
            uint32_t af[2][4];
            #pragma unroll
            for (int mf = 0; mf < 2; mf++)
                LDSM4(af[mf][0], af[mf][1], af[mf][2], af[mf][3],
                      (ab + Aoff[mf]) ^ cx);
            uint32_t bf[8][2];
            if (B_NN) {
                #pragma unroll
                for (int nfp = 0; nfp < 4; nfp++) {
                    uint32_t r0, r1, r2, r3;
                    LDSM4T(r0, r1, r2, r3, bb + Boff[nfp] + (uint32_t)(ks * 8192));
                    bf[2 * nfp][0] = r0;  bf[2 * nfp][1] = r1;
                    bf[2 * nfp + 1][0] = r2;  bf[2 * nfp + 1][1] = r3;
                }
            } else {
                #pragma unroll
                for (int nfp = 0; nfp < 4; nfp++) {
                    uint32_t r0, r1, r2, r3;
                    LDSM4(r0, r1, r2, r3, (bb + Boff[nfp]) ^ cx);
                    bf[2 * nfp][0] = r0;  bf[2 * nfp][1] = r1;
                    bf[2 * nfp + 1][0] = r2;  bf[2 * nfp + 1][1] = r3;
                }
            }
            #pragma unroll
            for (int mf = 0; mf < 2; mf++)
                #pragma unroll
                for (int nf = 0; nf < 8; nf++)
                    MMA_F16(acc[mf][nf][0], acc[mf][nf][1],
                            acc[mf][nf][2], acc[mf][nf][3],
                            af[mf][0], af[mf][1], af[mf][2], af[mf][3],
                            bf[nf][0], bf[nf][1]);
        }
    }

    // --- epilogue ---
    if (EXP_MODE) {
        // exp() of logits -> fp16 P', plus deterministic per-CTA row sums
        __shared__ float sh_part[4][TBM];
        __half* C = (__half*)Cv;
        const int wcol = w >> 2;     // 0..3 (warp column group)
        float rs0[2] = {0.f, 0.f};
        float rs1[2] = {0.f, 0.f};
        #pragma unroll
        for (int mf = 0; mf < 2; mf++) {
            const int r0 = bm + wm + mf * 16 + (lane >> 2);
            #pragma unroll
            for (int nf = 0; nf < 8; nf++) {
                const int c0 = bn + wn + nf * 8 + 2 * (lane & 3);
                const float e00 = __expf(acc[mf][nf][0] * scale);
                const float e01 = __expf(acc[mf][nf][1] * scale);
                const float e10 = __expf(acc[mf][nf][2] * scale);
                const float e11 = __expf(acc[mf][nf][3] * scale);
                rs0[mf] += e00 + e01;
                rs1[mf] += e10 + e11;
                *reinterpret_cast<__half2*>(C + (size_t)r0 * N + c0) =
                    __floats2half2_rn(e00, e01);
                *reinterpret_cast<__half2*>(C + (size_t)(r0 + 8) * N + c0) =
                    __floats2half2_rn(e10, e11);
            }
        }
        // quad reduce (sum over lane&3 within each quad) — deterministic
        #pragma unroll
        for (int mf = 0; mf < 2; mf++) {
            #pragma unroll
            for (int o = 1; o <= 2; o <<= 1) {
                rs0[mf] += __shfl_xor_sync(0xffffffffu, rs0[mf], o);
                rs1[mf] += __shfl_xor_sync(0xffffffffu, rs1[mf], o);
            }
        }
        if ((lane & 3) == 0) {
            #pragma unroll
            for (int mf = 0; mf < 2; mf++) {
                const int r = wm + mf * 16 + (lane >> 2);
                sh_part[wcol][r]     = rs0[mf];
                sh_part[wcol][r + 8] = rs1[mf];
            }
        }
        __syncthreads();
        if (tid < TBM) {
            rowpart[bm + tid] = (sh_part[0][tid] + sh_part[1][tid]) +
                                (sh_part[2][tid] + sh_part[3][tid]);
        }
    } else {
        #pragma unroll
        for (int mf = 0; mf < 2; mf++) {
            const int r0 = bm + wm + mf * 16 + (lane >> 2);
            float ri0 = 1.f, ri1 = 1.f;
            if (ROWSCALE) { ri0 = rinv[r0]; ri1 = rinv[r0 + 8]; }
            #pragma unroll
            for (int nf = 0; nf < 8; nf++) {
                const int c0 = bn + wn + nf * 8 + 2 * (lane & 3);
                float2 b2 = make_float2(0.f, 0.f);
                if (HAS_BIAS) b2 = *reinterpret_cast<const float2*>(bias + c0);
                float v00 = acc[mf][nf][0] * scale + b2.x;
                float v01 = acc[mf][nf][1] * scale + b2.y;
                float v10 = acc[mf][nf][2] * scale + b2.x;
                float v11 = acc[mf][nf][3] * scale + b2.y;
                if (ROWSCALE) { v00 *= ri0; v01 *= ri0; v10 *= ri1; v11 *= ri1; }
                if (OUT_HALF) {
                    __half* C = (__half*)Cv;
                    *reinterpret_cast<__half2*>(C + (size_t)r0 * N + c0) =
                        __floats2half2_rn(v00, v01);
                    *reinterpret_cast<__half2*>(C + (size_t)(r0 + 8) * N + c0) =
                        __floats2half2_rn(v10, v11);
                } else {
                    float* C = (float*)Cv;
                    *reinterpret_cast<float2*>(C + (size_t)r0 * N + c0) =
                        make_float2(v00, v01);
                    *reinterpret_cast<float2*>(C + (size_t)(r0 + 8) * N + c0) =
                        make_float2(v10, v11);
                }
            }
        }
    }
}

// Fused QKV projection: one launch, grid.z in {0,1,2} selects operand set.
__global__ __launch_bounds__(NTHR, 1)
void qkv_proj_kernel(const __half* __restrict__ ln_t, const __half* __restrict__ ln_k,
                     const __half* __restrict__ ln_v,
                     const __half* __restrict__ wq, const __half* __restrict__ wk,
                     const __half* __restrict__ wv,
                     const float* __restrict__ bq, const float* __restrict__ bk,
                     const float* __restrict__ bv,
                     __half* __restrict__ q, __half* __restrict__ k,
                     __half* __restrict__ v) {
    const int z = blockIdx.z;
    const __half* A  = (z == 0) ? ln_t : (z == 1) ? ln_k : ln_v;
    const __half* Bm = (z == 0) ? wq   : (z == 1) ? wk   : wv;
    const float* bias = (z == 0) ? bq  : (z == 1) ? bk   : bv;
    __half* C = (z == 0) ? q : (z == 1) ? k : v;
    gemm_body<true, true, false, false, false>(A, Bm, bias, C, DIM_, DIM_, 1.0f,
                                               blockIdx.y * TBM, blockIdx.x * TBN,
                                               nullptr, nullptr);
}

// QK^T with exp epilogue: P' = exp(scale * Q K^T), partial row sums out.
__global__ __launch_bounds__(NTHR, 1)
void qk_exp_kernel(const __half* __restrict__ q, const __half* __restrict__ k,
                   __half* __restrict__ P, float* __restrict__ Spart) {
    const int z = blockIdx.z;
    const __half* A = q + (size_t)z * TI_ * DIM_;
    const __half* B = k + (size_t)z * TJ_ * DIM_;
    __half* C = P + (size_t)z * TI_ * TJ_;
    float* rowpart = Spart + (size_t)blockIdx.x * NROWS_T + (size_t)z * TI_;
    gemm_body<false, true, true, false, false>(A, B, nullptr, C, TJ_, DIM_, 0.03125f,
                                               blockIdx.y * TBM, blockIdx.x * TBN,
                                               rowpart, nullptr);
}

// PV with per-row normalization: O = (P' V) * rinv[row]; V read NN via
// ldmatrix.trans (no transpose pass).
__global__ __launch_bounds__(NTHR, 1)
void pv_kernel(const __half* __restrict__ P, const __half* __restrict__ v,
               float* __restrict__ out, const float* __restrict__ rinv) {
    const int z = blockIdx.z;
    const __half* A = P + (size_t)z * TI_ * TJ_;
    const __half* B = v + (size_t)z * TJ_ * DIM_;   // [K=TJ][N=DIM] row-major
    float* C = out + (size_t)z * TI_ * DIM_;
    gemm_body<false, false, false, true, true>(A, B, nullptr, C, DIM_, TJ_, 1.0f,
                                               blockIdx.y * TBM, blockIdx.x * TBN,
                                               nullptr, rinv + (size_t)z * TI_);
}

// ---------------------------------------------------------------------------
// Row-sum reduction: rinv[r] = 1 / sum_x Spart[x][r]   (deterministic order)
// ---------------------------------------------------------------------------
__global__ void rowinv_kernel(const float* __restrict__ Spart,
                              float* __restrict__ rinv) {
    const int r = blockIdx.x * blockDim.x + threadIdx.x;
    if (r < NROWS_T) {
        float s = 0.f;
        #pragma unroll
        for (int x = 0; x < NXT_; x++) s += Spart[(size_t)x * NROWS_T + r];
        rinv[r] = 1.0f / s;
    }
}

// ---------------------------------------------------------------------------
// Fused fp32 -> fp16 (RN) weight conversion: grid.z selects matrix
// ---------------------------------------------------------------------------
__global__ void cvt3_kernel(const float* __restrict__ w0, const float* __restrict__ w1,
                            const float* __restrict__ w2,
                            __half* __restrict__ o0, __half* __restrict__ o1,
                            __half* __restrict__ o2) {
    const int z = blockIdx.z;
    const float* in = (z == 0) ? w0 : (z == 1) ? w1 : w2;
    __half* out     = (z == 0) ? o0 : (z == 1) ? o1 : o2;
    const int i = blockIdx.x * blockDim.x + threadIdx.x;
    const float4 v = reinterpret_cast<const float4*>(in)[i];
    const __half2 h0 = __floats2half2_rn(v.x, v.y);
    const __half2 h1 = __floats2half2_rn(v.z, v.w);
    uint2 u;
    u.x = *reinterpret_cast<const uint32_t*>(&h0);
    u.y = *reinterpret_cast<const uint32_t*>(&h1);
    reinterpret_cast<uint2*>(out)[i] = u;
}

// ---------------------------------------------------------------------------
// Fused LayerNorm, TWO-PASS: one WARP per row of 1024 (8 rows/block).
// Pass 1 streams x once for mean/var (no register caching); pass 2 re-reads
// x (L2-resident, 4 KB/row) and writes fp16. ~30 regs -> ~2x occupancy vs
// the xv[8]-cached version (regs=62, occ 43%).
// ---------------------------------------------------------------------------
__global__ __launch_bounds__(256)
void ln3_kernel(const float* __restrict__ x0, const float* __restrict__ x1,
                const float* __restrict__ x2,
                const float* __restrict__ g0, const float* __restrict__ b0,
                const float* __restrict__ g1, const float* __restrict__ b1,
                const float* __restrict__ g2, const float* __restrict__ b2,
                __half* __restrict__ o0, __half* __restrict__ o1,
                __half* __restrict__ o2) {
    const int z = blockIdx.z;
    const float* x     = (z == 0) ? x0 : (z == 1) ? x1 : x2;
    const float* gamma = (z == 0) ? g0 : (z == 1) ? g1 : g2;
    const float* beta  = (z == 0) ? b0 : (z == 1) ? b1 : b2;
    __half* out        = (z == 0) ? o0 : (z == 1) ? o1 : o2;

    const int warp = threadIdx.x >> 5, lane = threadIdx.x & 31;
    const size_t row = (size_t)blockIdx.x * 8 + warp;
    const float4* xr = reinterpret_cast<const float4*>(x + row * DIM_);

    // pass 1: streaming reduction (registers reused each iteration)
    float s = 0.f, s2 = 0.f;
    #pragma unroll
    for (int i = 0; i < 8; i++) {
        const float4 xv = xr[lane + 32 * i];
        s  += xv.x + xv.y + xv.z + xv.w;
        s2 += xv.x*xv.x + xv.y*xv.y + xv.z*xv.z + xv.w*xv.w;
    }
    #pragma unroll
    for (int o = 16; o; o >>= 1) {
        s  += __shfl_xor_sync(0xffffffffu, s,  o);
        s2 += __shfl_xor_sync(0xffffffffu, s2, o);
    }
    const float mean = s * (1.0f / DIM_);
    const float var  = s2 * (1.0f / DIM_) - mean * mean;
    const float inv  = rsqrtf(var + EPS_);

    // pass 2: re-read (L2 hit), normalize, store fp16
    uint2* o2v = reinterpret_cast<uint2*>(out + row * DIM_);
    #pragma unroll
    for (int i = 0; i < 8; i++) {
        const float4 xv = xr[lane + 32 * i];
        const float4 gv = reinterpret_cast<const float4*>(gamma)[lane + 32 * i];
        const float4 bv = reinterpret_cast<const float4*>(beta)[lane + 32 * i];
        const __half2 h0 = __floats2half2_rn((xv.x - mean) * inv * gv.x + bv.x,
                                             (xv.y - mean) * inv * gv.y + bv.y);
        const __half2 h1 = __floats2half2_rn((xv.z - mean) * inv * gv.z + bv.z,
                                             (xv.w - mean) * inv * gv.w + bv.w);
        uint2 u;
        u.x = *reinterpret_cast<const uint32_t*>(&h0);
        u.y = *reinterpret_cast<const uint32_t*>(&h1);
        o2v[lane + 32 * i] = u;
    }
}

// ---------------------------------------------------------------------------
// Launch
// ---------------------------------------------------------------------------
extern "C" void kernel_launch(void* const* d_in, const int* in_sizes, int n_in,
                              void* d_out, int out_size) {
    (void)in_sizes; (void)n_in; (void)out_size;
    const float* target   = (const float*)d_in[0];
    const float* source_k = (const float*)d_in[1];
    const float* source_v = (const float*)d_in[2];
    const float* Wq = (const float*)d_in[3];
    const float* bq = (const float*)d_in[4];
    const float* Wk = (const float*)d_in[5];
    const float* bk = (const float*)d_in[6];
    const float* Wv = (const float*)d_in[7];
    const float* bv = (const float*)d_in[8];
    const float* gt = (const float*)d_in[9];
    const float* bt = (const float*)d_in[10];
    const float* gk = (const float*)d_in[11];
    const float* bk_ln = (const float*)d_in[12];
    const float* gv = (const float*)d_in[13];
    const float* bv_ln = (const float*)d_in[14];
    float* out = (float*)d_out;

    __half *ln_t, *ln_k, *ln_v, *q, *k, *v, *P, *wq_h, *wk_h, *wv_h;
    float *Spart, *rinv;
    cudaGetSymbolAddress((void**)&ln_t, g_ln_t);
    cudaGetSymbolAddress((void**)&ln_k, g_ln_k);
    cudaGetSymbolAddress((void**)&ln_v, g_ln_v);
    cudaGetSymbolAddress((void**)&q,    g_q);
    cudaGetSymbolAddress((void**)&k,    g_k);
    cudaGetSymbolAddress((void**)&v,    g_v);
    cudaGetSymbolAddress((void**)&P,    g_P);
    cudaGetSymbolAddress((void**)&Spart, g_Spart);
    cudaGetSymbolAddress((void**)&rinv,  g_rinv);
    cudaGetSymbolAddress((void**)&wq_h, g_Wq);
    cudaGetSymbolAddress((void**)&wk_h, g_Wk);
    cudaGetSymbolAddress((void**)&wv_h, g_Wv);

    cudaFuncSetAttribute(qkv_proj_kernel,
        cudaFuncAttributeMaxDynamicSharedMemorySize, SMEM_TOTAL_GEMM);
    cudaFuncSetAttribute(qk_exp_kernel,
        cudaFuncAttributeMaxDynamicSharedMemorySize, SMEM_TOTAL_GEMM);
    cudaFuncSetAttribute(pv_kernel,
        cudaFuncAttributeMaxDynamicSharedMemorySize, SMEM_TOTAL_GEMM);

    // Weights -> fp16 (one launch)
    cvt3_kernel<<<dim3(DIM_ * DIM_ / 4 / 256, 1, 3), 256>>>(
        Wq, Wk, Wv, wq_h, wk_h, wv_h);

    // LayerNorms (one launch, two-pass warp-per-row, fp16 out)
    ln3_kernel<<<dim3(NROWS_T / 8, 1, 3), 256>>>(
        target, source_k, source_v,
        gt, bt, gk, bk_ln, gv, bv_ln,
        ln_t, ln_k, ln_v);

    // Fused Q/K/V projections: one launch of 1536 CTAs (TN=256, R10 config)
    qkv_proj_kernel<<<dim3(DIM_ / TBN, NROWS_T / TBM, 3), NTHR, SMEM_TOTAL_GEMM>>>(
        ln_t, ln_k, ln_v, wq_h, wk_h, wv_h, bq, bk, bv, q, k, v);

    // P' = exp((Q K^T) * DIM^-0.5)  (fp16) + per-x-tile row sums
    dim3 gS(TJ_ / TBN, TI_ / TBM, B_);
    qk_exp_kernel<<<gS, NTHR, SMEM_TOTAL_GEMM>>>(q, k, P, Spart);

    // rinv[r] = 1 / sum of partials
    rowinv_kernel<<<(NROWS_T + 255) / 256, 256>>>(Spart, rinv);

    // O = (P' V) * rinv, batched (fp32 out to d_out), V read NN
    dim3 gO(DIM_ / TBN, TI_ / TBM, B_);
    pv_kernel<<<gO, NTHR, SMEM_TOTAL_GEMM>>>(P, v, out, rinv);
}